// round 15
// baseline (speedup 1.0000x reference)
#include <cuda_runtime.h>
#include <cuda_fp16.h>
#include <math.h>
#include <stdint.h>

// Problem constants (B=1)
#define SEQ   2048
#define HID   4096
#define NHEAD 32
#define HDIM  128
#define QKV_N 12288            // 3*HID
#define INV_NORM 0.08838834764831845f   // 1/sqrt(128)

// Scratch buffers (device globals; runtime alloc forbidden)
static __device__ __half g_qkv_h[(size_t)SEQ * QKV_N];
static __device__ __half g_A_h[(size_t)SEQ * HID];   // hs fp16, later overwritten by ctx

// ---------------------------------------------------------------------------
// helpers
// ---------------------------------------------------------------------------
__device__ __forceinline__ uint32_t smem_u32(const void* p) {
    uint32_t a;
    asm("{ .reg .u64 t; cvta.to.shared.u64 t, %1; cvt.u32.u64 %0, t; }" : "=r"(a) : "l"(p));
    return a;
}
__device__ __forceinline__ void ldsm4(uint32_t* r, uint32_t addr) {
    asm volatile("ldmatrix.sync.aligned.m8n8.x4.shared.b16 {%0,%1,%2,%3}, [%4];"
                 : "=r"(r[0]), "=r"(r[1]), "=r"(r[2]), "=r"(r[3]) : "r"(addr));
}
__device__ __forceinline__ void ldsm4t(uint32_t* r, uint32_t addr) {
    asm volatile("ldmatrix.sync.aligned.m8n8.x4.trans.shared.b16 {%0,%1,%2,%3}, [%4];"
                 : "=r"(r[0]), "=r"(r[1]), "=r"(r[2]), "=r"(r[3]) : "r"(addr));
}
__device__ __forceinline__ void mma16816(float* c, const uint32_t* a, const uint32_t* b) {
    asm volatile(
        "mma.sync.aligned.m16n8k16.row.col.f32.f16.f16.f32 "
        "{%0,%1,%2,%3}, {%4,%5,%6,%7}, {%8,%9}, {%0,%1,%2,%3};"
        : "+f"(c[0]), "+f"(c[1]), "+f"(c[2]), "+f"(c[3])
        : "r"(a[0]), "r"(a[1]), "r"(a[2]), "r"(a[3]), "r"(b[0]), "r"(b[1]));
}
__device__ __forceinline__ void cp16(uint32_t dst, const void* src) {
    asm volatile("cp.async.cg.shared.global [%0], [%1], 16;" :: "r"(dst), "l"(src) : "memory");
}
__device__ __forceinline__ void cp_commit() {
    asm volatile("cp.async.commit_group;" ::: "memory");
}
template <int N>
__device__ __forceinline__ void cp_wait() {
    asm volatile("cp.async.wait_group %0;" :: "n"(N) : "memory");
}

// ---------------------------------------------------------------------------
// fp32 -> fp16 round (grid-stride, float4) — only used for hidden_states now
// ---------------------------------------------------------------------------
__global__ void round16_kernel(const float* __restrict__ x, __half* __restrict__ h, int n)
{
    const int stride = gridDim.x * blockDim.x * 4;
    for (int i = (blockIdx.x * blockDim.x + threadIdx.x) * 4; i < n; i += stride) {
        const float4 v = *(const float4*)(x + i);
        __half2 h0 = __floats2half2_rn(v.x, v.y);
        __half2 h1 = __floats2half2_rn(v.z, v.w);
        *(uint2*)(h + i) = make_uint2(*(uint32_t*)&h0, *(uint32_t*)&h1);
    }
}

// ---------------------------------------------------------------------------
// fp16 HMMA TN GEMM; A fp16 via 4-stage cp.async, B fp32 weights converted
// in-kernel (LDG float4 -> cvt -> STS), single B buffer, two-barrier chunk.
// 512 threads (16 warps, 4m x 4n, warp tile 32x32), CTA tile 128x128, BK=32.
// C[m,n] = sum_k A[m,k]*B[n,k] + bias[n] (+ add[m,n]); out fp32 or fp16.
// ---------------------------------------------------------------------------
#define SSTRIDE 40
#define STAGES 4
#define BK 32
#define BUF_BYTES (128 * SSTRIDE * 2)          // 10240
#define GSM_TOTAL (STAGES * BUF_BYTES + BUF_BYTES)   // 4 A stages + 1 B buffer = 51200

template <bool HALF_OUT>
__global__ __launch_bounds__(512, 1)
void gemm_hmma(const __half* __restrict__ Ag, const float* __restrict__ Bg32,
               const float* __restrict__ bias, const float* __restrict__ add,
               void* __restrict__ Cv, int M, int N, int K)
{
    extern __shared__ char smem[];
    const uint32_t sb = smem_u32(smem);
    const uint32_t sbB = sb + STAGES * BUF_BYTES;

    const int tid  = threadIdx.x;
    const int wid  = tid >> 5;
    const int lane = tid & 31;
    const int bm = blockIdx.y * 128;
    const int bn = blockIdx.x * 128;

    const int warp_m = (wid & 3) * 32;
    const int warp_n = (wid >> 2) * 32;

    // loader mapping: thread -> row (0..127), 8-col segment (0..3)
    const int lrow = tid >> 2;
    const int lcol = (tid & 3) * 8;
    const __half* gA  = Ag   + (size_t)(bm + lrow) * K + lcol;
    const float*  gB  = Bg32 + (size_t)(bn + lrow) * K + lcol;
    const uint32_t sdst = (uint32_t)(lrow * SSTRIDE + lcol) * 2;

    // ldmatrix lane addressing (validated)
    const int a_r = warp_m + (lane & 15);
    const int a_c = (lane >> 4) * 8;
    const int b_r = warp_n + (lane >> 4) * 8 + (lane & 7);
    const int b_c = ((lane >> 3) & 1) * 8;

    float acc[2][4][4];
#pragma unroll
    for (int i = 0; i < 2; i++)
#pragma unroll
        for (int j = 0; j < 4; j++)
#pragma unroll
            for (int e = 0; e < 4; e++) acc[i][j][e] = 0.0f;

    const int NCH = K / BK;

    auto issueA = [&](int ch) {
        const uint32_t base = sb + (uint32_t)(ch % STAGES) * BUF_BYTES;
        cp16(base + sdst, gA + ch * BK);
        cp_commit();
    };

#pragma unroll
    for (int ch = 0; ch < STAGES - 1; ch++) issueA(ch);

    // prefetch B chunk 0 (fp32, 8 floats per thread)
    float4 pb0 = *(const float4*)(gB);
    float4 pb1 = *(const float4*)(gB + 4);

    for (int ch = 0; ch < NCH; ch++) {
        cp_wait<STAGES - 2>();
        __syncthreads();                       // A[ch] resident; B buffer free
        if (ch + STAGES - 1 < NCH) issueA(ch + STAGES - 1);

        // convert + store B chunk ch
        {
            __half2 h0 = __floats2half2_rn(pb0.x, pb0.y);
            __half2 h1 = __floats2half2_rn(pb0.z, pb0.w);
            __half2 h2 = __floats2half2_rn(pb1.x, pb1.y);
            __half2 h3 = __floats2half2_rn(pb1.z, pb1.w);
            uint4 v = make_uint4(*(uint32_t*)&h0, *(uint32_t*)&h1,
                                 *(uint32_t*)&h2, *(uint32_t*)&h3);
            *(uint4*)(smem + (STAGES * BUF_BYTES) + sdst) = v;
        }
        __syncthreads();                       // B[ch] visible to all warps

        // prefetch B chunk ch+1 (overlaps MMAs)
        if (ch + 1 < NCH) {
            const int ko = (ch + 1) * BK;
            pb0 = *(const float4*)(gB + ko);
            pb1 = *(const float4*)(gB + ko + 4);
        }

        const uint32_t aA = sb + (uint32_t)(ch % STAGES) * BUF_BYTES;

#pragma unroll
        for (int ks = 0; ks < 2; ks++) {
            const int kc = ks * 16;
            uint32_t ah[2][4], bh[4][2];
#pragma unroll
            for (int mt = 0; mt < 2; mt++) {
                const uint32_t off = (uint32_t)(((a_r + mt * 16) * SSTRIDE + kc + a_c) * 2);
                ldsm4(ah[mt], aA + off);
            }
#pragma unroll
            for (int ntp = 0; ntp < 2; ntp++) {
                const uint32_t off = (uint32_t)(((b_r + ntp * 16) * SSTRIDE + kc + b_c) * 2);
                uint32_t r[4];
                ldsm4(r, sbB + off);
                bh[ntp * 2][0] = r[0]; bh[ntp * 2][1] = r[1];
                bh[ntp * 2 + 1][0] = r[2]; bh[ntp * 2 + 1][1] = r[3];
            }
#pragma unroll
            for (int mt = 0; mt < 2; mt++)
#pragma unroll
                for (int nt = 0; nt < 4; nt++)
                    mma16816(acc[mt][nt], ah[mt], bh[nt]);
        }
    }

    // epilogue
#pragma unroll
    for (int mt = 0; mt < 2; mt++) {
        const int r0 = bm + warp_m + mt * 16 + (lane >> 2);
#pragma unroll
        for (int nt = 0; nt < 4; nt++) {
            const int col = bn + warp_n + nt * 8 + (lane & 3) * 2;
            const float b0 = bias[col], b1 = bias[col + 1];
            const float* c = acc[mt][nt];
            const size_t o0 = (size_t)r0 * N + col;
            const size_t o1 = (size_t)(r0 + 8) * N + col;
            float2 v0 = make_float2(c[0] + b0, c[1] + b1);
            float2 v1 = make_float2(c[2] + b0, c[3] + b1);
            if (add != nullptr) {
                const float2 a0 = *(const float2*)&add[o0];
                const float2 a1 = *(const float2*)&add[o1];
                v0.x += a0.x; v0.y += a0.y;
                v1.x += a1.x; v1.y += a1.y;
            }
            if (HALF_OUT) {
                __half* C = (__half*)Cv;
                *(__half2*)&C[o0] = __floats2half2_rn(v0.x, v0.y);
                *(__half2*)&C[o1] = __floats2half2_rn(v1.x, v1.y);
            } else {
                float* C = (float*)Cv;
                *(float2*)&C[o0] = v0;
                *(float2*)&C[o1] = v1;
            }
        }
    }
}

// ---------------------------------------------------------------------------
// Tensor-core flash attention with ALiBi (fp16 inputs, fp32 softmax/accum).
// (unchanged from R11 — passed at rel_err 4.1e-4)
// ---------------------------------------------------------------------------
#define VSTRIDE 136
#define KTILE_B (64 * VSTRIDE * 2)
#define STAGE_A (2 * KTILE_B + 256)
#define ATT_SMEM (2 * STAGE_A)

__global__ __launch_bounds__(128, 1)
void attn_hmma(const __half* __restrict__ qkv, const float* __restrict__ alibi,
               __half* __restrict__ ctx)
{
    extern __shared__ char smem[];
    const uint32_t sb = smem_u32(smem);
    const int h = blockIdx.y, qb = blockIdx.x;
    const int tid = threadIdx.x, wid = tid >> 5, lane = tid & 31;
    const int qw0 = qb * 64 + wid * 16;
    const int r0 = lane >> 2;
    const int c0 = (lane & 3) * 2;

    uint32_t qf[8][4];
    {
        const __half* qbase = qkv + (size_t)qw0 * QKV_N + h * 384;
#pragma unroll
        for (int ks = 0; ks < 8; ks++) {
            const int col = ks * 16 + c0;
            qf[ks][0] = *(const uint32_t*)(qbase + (size_t)r0 * QKV_N + col);
            qf[ks][1] = *(const uint32_t*)(qbase + (size_t)(r0 + 8) * QKV_N + col);
            qf[ks][2] = *(const uint32_t*)(qbase + (size_t)r0 * QKV_N + col + 8);
            qf[ks][3] = *(const uint32_t*)(qbase + (size_t)(r0 + 8) * QKV_N + col + 8);
        }
    }

    float oacc[16][4];
#pragma unroll
    for (int i = 0; i < 16; i++)
#pragma unroll
        for (int e = 0; e < 4; e++) oacc[i][e] = 0.0f;
    float mr0 = -INFINITY, mr1 = -INFINITY, ls0 = 0.0f, ls1 = 0.0f;

    const int nt = qb + 1;

    auto issue = [&](int t) {
        const uint32_t base = sb + (uint32_t)(t & 1) * STAGE_A;
        const int kv0 = t * 64;
        const int r = tid >> 1, chl = tid & 1;
        const __half* ksrc = qkv + (size_t)(kv0 + r) * QKV_N + h * 384 + 128 + chl * 64;
        const uint32_t kdst = base + (uint32_t)(r * VSTRIDE + chl * 64) * 2;
#pragma unroll
        for (int c = 0; c < 8; c++) {
            cp16(kdst + c * 16,           ksrc + c * 8);
            cp16(kdst + KTILE_B + c * 16, ksrc + 128 + c * 8);
        }
        if (tid < 16)
            cp16(base + 2 * KTILE_B + tid * 16,
                 alibi + (size_t)h * SEQ + kv0 + tid * 4);
        cp_commit();
    };

    issue(0);

    for (int t = 0; t < nt; t++) {
        cp_wait<0>();
        __syncthreads();
        if (t + 1 < nt) issue(t + 1);

        const uint32_t base = sb + (uint32_t)(t & 1) * STAGE_A;
        const uint32_t Ks = base, Vs = base + KTILE_B;
        const float* albuf = (const float*)(smem + (size_t)(t & 1) * STAGE_A + 2 * KTILE_B);

        float sacc[8][4];
#pragma unroll
        for (int i = 0; i < 8; i++)
#pragma unroll
            for (int e = 0; e < 4; e++) sacc[i][e] = 0.0f;

#pragma unroll
        for (int ks = 0; ks < 8; ks++) {
            const int kc = ks * 16;
#pragma unroll
            for (int ntp = 0; ntp < 4; ntp++) {
                uint32_t rr[4];
                const uint32_t addr = Ks +
                    (uint32_t)(((ntp * 16 + (lane >> 4) * 8 + (lane & 7)) * VSTRIDE
                                + kc + ((lane >> 3) & 1) * 8) * 2);
                ldsm4(rr, addr);
                uint32_t b0[2] = {rr[0], rr[1]}, b1[2] = {rr[2], rr[3]};
                mma16816(sacc[2 * ntp],     qf[ks], b0);
                mma16816(sacc[2 * ntp + 1], qf[ks], b1);
            }
        }

        const int kv0 = t * 64;
        const int qg0 = qw0 + r0, qg1 = qg0 + 8;
        float m0 = -INFINITY, m1 = -INFINITY;
#pragma unroll
        for (int n8 = 0; n8 < 8; n8++) {
            const int j0 = n8 * 8 + c0;
            const float a0 = albuf[j0], a1 = albuf[j0 + 1];
            const int jg0 = kv0 + j0;
            float v0 = sacc[n8][0] * INV_NORM + a0;
            float v1 = sacc[n8][1] * INV_NORM + a1;
            float v2 = sacc[n8][2] * INV_NORM + a0;
            float v3 = sacc[n8][3] * INV_NORM + a1;
            if (jg0     > qg0) v0 = -INFINITY;
            if (jg0 + 1 > qg0) v1 = -INFINITY;
            if (jg0     > qg1) v2 = -INFINITY;
            if (jg0 + 1 > qg1) v3 = -INFINITY;
            sacc[n8][0] = v0; sacc[n8][1] = v1; sacc[n8][2] = v2; sacc[n8][3] = v3;
            m0 = fmaxf(m0, fmaxf(v0, v1));
            m1 = fmaxf(m1, fmaxf(v2, v3));
        }
        m0 = fmaxf(m0, __shfl_xor_sync(0xffffffffu, m0, 1));
        m0 = fmaxf(m0, __shfl_xor_sync(0xffffffffu, m0, 2));
        m1 = fmaxf(m1, __shfl_xor_sync(0xffffffffu, m1, 1));
        m1 = fmaxf(m1, __shfl_xor_sync(0xffffffffu, m1, 2));
        const float nm0 = fmaxf(mr0, m0), nm1 = fmaxf(mr1, m1);
        const float f0 = __expf(mr0 - nm0), f1 = __expf(mr1 - nm1);
        mr0 = nm0; mr1 = nm1;
        ls0 *= f0; ls1 *= f1;
#pragma unroll
        for (int i = 0; i < 16; i++) {
            oacc[i][0] *= f0; oacc[i][1] *= f0;
            oacc[i][2] *= f1; oacc[i][3] *= f1;
        }

        uint32_t pf[4][4];
#pragma unroll
        for (int n8 = 0; n8 < 8; n8++) {
            const float p0 = __expf(sacc[n8][0] - nm0);
            const float p1 = __expf(sacc[n8][1] - nm0);
            const float p2 = __expf(sacc[n8][2] - nm1);
            const float p3 = __expf(sacc[n8][3] - nm1);
            ls0 += p0 + p1; ls1 += p2 + p3;
            __half2 h01 = __floats2half2_rn(p0, p1);
            __half2 h23 = __floats2half2_rn(p2, p3);
            const int ks = n8 >> 1, hi = n8 & 1;
            pf[ks][2 * hi]     = *(uint32_t*)&h01;
            pf[ks][2 * hi + 1] = *(uint32_t*)&h23;
        }

#pragma unroll
        for (int ks = 0; ks < 4; ks++) {
#pragma unroll
            for (int g = 0; g < 8; g++) {
                uint32_t rr[4];
                const uint32_t addr = Vs +
                    (uint32_t)(((ks * 16 + ((lane >> 3) & 1) * 8 + (lane & 7)) * VSTRIDE
                                + g * 16 + (lane >> 4) * 8) * 2);
                ldsm4t(rr, addr);
                uint32_t b0[2] = {rr[0], rr[1]}, b1[2] = {rr[2], rr[3]};
                mma16816(oacc[2 * g],     pf[ks], b0);
                mma16816(oacc[2 * g + 1], pf[ks], b1);
            }
        }
    }

    ls0 += __shfl_xor_sync(0xffffffffu, ls0, 1);
    ls0 += __shfl_xor_sync(0xffffffffu, ls0, 2);
    ls1 += __shfl_xor_sync(0xffffffffu, ls1, 1);
    ls1 += __shfl_xor_sync(0xffffffffu, ls1, 2);
    const float inv0 = 1.0f / ls0, inv1 = 1.0f / ls1;

    __half* out0 = ctx + (size_t)(qw0 + r0) * HID + h * HDIM;
    __half* out1 = out0 + (size_t)8 * HID;
#pragma unroll
    for (int nd = 0; nd < 16; nd++) {
        const int d = nd * 8 + c0;
        *(__half2*)(out0 + d) = __floats2half2_rn(oacc[nd][0] * inv0, oacc[nd][1] * inv0);
        *(__half2*)(out1 + d) = __floats2half2_rn(oacc[nd][2] * inv1, oacc[nd][3] * inv1);
    }
}

// ---------------------------------------------------------------------------
// Launch
// inputs: 0 hidden_states, 1 residual, 2 alibi, 3 attention_mask (unused),
//         4 W_qkv [12288,4096], 5 b_qkv, 6 W_dense [4096,4096], 7 b_dense
// ---------------------------------------------------------------------------
extern "C" void kernel_launch(void* const* d_in, const int* in_sizes, int n_in,
                              void* d_out, int out_size)
{
    const float* hs       = (const float*)d_in[0];
    const float* residual = (const float*)d_in[1];
    const float* alibi    = (const float*)d_in[2];
    const float* Wqkv     = (const float*)d_in[4];
    const float* bqkv     = (const float*)d_in[5];
    const float* Wd       = (const float*)d_in[6];
    const float* bd       = (const float*)d_in[7];
    float* out = (float*)d_out;

    __half *qkv_h, *a_h;
    cudaGetSymbolAddress((void**)&qkv_h, g_qkv_h);
    cudaGetSymbolAddress((void**)&a_h, g_A_h);

    cudaFuncSetAttribute(gemm_hmma<true>,  cudaFuncAttributeMaxDynamicSharedMemorySize, GSM_TOTAL);
    cudaFuncSetAttribute(gemm_hmma<false>, cudaFuncAttributeMaxDynamicSharedMemorySize, GSM_TOTAL);
    cudaFuncSetAttribute(attn_hmma, cudaFuncAttributeMaxDynamicSharedMemorySize, ATT_SMEM);

    // 0) convert hidden_states to fp16 (weights converted in-GEMM now)
    round16_kernel<<<1024, 256>>>(hs, a_h, SEQ * HID);

    // 1) fused QKV projection -> fp16 qkv (W_qkv fp32 converted in-kernel)
    {
        dim3 grid(QKV_N / 128, SEQ / 128);
        gemm_hmma<true><<<grid, 512, GSM_TOTAL>>>(a_h, Wqkv, bqkv, nullptr,
                                                  qkv_h, SEQ, QKV_N, HID);
    }
    // 2) tensor-core flash attention -> ctx fp16 (overwrites a_h)
    {
        dim3 grid(SEQ / 64, NHEAD);
        attn_hmma<<<grid, 128, ATT_SMEM>>>(qkv_h, alibi, a_h);
    }
    // 3) dense projection + bias + residual -> fp32 out (W_dense fp32 in-kernel)
    {
        dim3 grid(HID / 128, SEQ / 128);
        gemm_hmma<false><<<grid, 512, GSM_TOTAL>>>(a_h, Wd, bd, residual,
                                                   out, SEQ, HID, HID);
    }
}

// round 16
// speedup vs baseline: 1.3123x; 1.3123x over previous
#include <cuda_runtime.h>
#include <cuda_fp16.h>
#include <math.h>
#include <stdint.h>

// Problem constants (B=1)
#define SEQ   2048
#define HID   4096
#define NHEAD 32
#define HDIM  128
#define QKV_N 12288            // 3*HID
#define INV_NORM 0.08838834764831845f   // 1/sqrt(128)

// Scratch buffers (device globals; runtime alloc forbidden)
static __device__ __half g_qkv_h[(size_t)SEQ * QKV_N];
static __device__ __half g_Wqkv_h[(size_t)QKV_N * HID];
static __device__ __half g_Wd_h[(size_t)HID * HID];
static __device__ __half g_A_h[(size_t)SEQ * HID];   // hs fp16, later overwritten by ctx

// ---------------------------------------------------------------------------
// helpers
// ---------------------------------------------------------------------------
__device__ __forceinline__ uint32_t smem_u32(const void* p) {
    uint32_t a;
    asm("{ .reg .u64 t; cvta.to.shared.u64 t, %1; cvt.u32.u64 %0, t; }" : "=r"(a) : "l"(p));
    return a;
}
__device__ __forceinline__ void ldsm4(uint32_t* r, uint32_t addr) {
    asm volatile("ldmatrix.sync.aligned.m8n8.x4.shared.b16 {%0,%1,%2,%3}, [%4];"
                 : "=r"(r[0]), "=r"(r[1]), "=r"(r[2]), "=r"(r[3]) : "r"(addr));
}
__device__ __forceinline__ void ldsm4t(uint32_t* r, uint32_t addr) {
    asm volatile("ldmatrix.sync.aligned.m8n8.x4.trans.shared.b16 {%0,%1,%2,%3}, [%4];"
                 : "=r"(r[0]), "=r"(r[1]), "=r"(r[2]), "=r"(r[3]) : "r"(addr));
}
__device__ __forceinline__ void mma16816(float* c, const uint32_t* a, const uint32_t* b) {
    asm volatile(
        "mma.sync.aligned.m16n8k16.row.col.f32.f16.f16.f32 "
        "{%0,%1,%2,%3}, {%4,%5,%6,%7}, {%8,%9}, {%0,%1,%2,%3};"
        : "+f"(c[0]), "+f"(c[1]), "+f"(c[2]), "+f"(c[3])
        : "r"(a[0]), "r"(a[1]), "r"(a[2]), "r"(a[3]), "r"(b[0]), "r"(b[1]));
}
__device__ __forceinline__ void cp16(uint32_t dst, const void* src) {
    asm volatile("cp.async.cg.shared.global [%0], [%1], 16;" :: "r"(dst), "l"(src) : "memory");
}
__device__ __forceinline__ void cp_commit() {
    asm volatile("cp.async.commit_group;" ::: "memory");
}
template <int N>
__device__ __forceinline__ void cp_wait() {
    asm volatile("cp.async.wait_group %0;" :: "n"(N) : "memory");
}

__device__ __forceinline__ void cvt4(const float* __restrict__ x, __half* __restrict__ h, int i) {
    const float4 v = *(const float4*)(x + i);
    __half2 h0 = __floats2half2_rn(v.x, v.y);
    __half2 h1 = __floats2half2_rn(v.z, v.w);
    *(uint2*)(h + i) = make_uint2(*(uint32_t*)&h0, *(uint32_t*)&h1);
}

// ---------------------------------------------------------------------------
// fp32 -> fp16 round for TWO arrays in one launch (Wqkv + hs)
// ---------------------------------------------------------------------------
__global__ void round16_dual_kernel(const float* __restrict__ x0, __half* __restrict__ h0, int n0,
                                    const float* __restrict__ x1, __half* __restrict__ h1, int n1)
{
    const int stride = gridDim.x * blockDim.x * 4;
    const int base = (blockIdx.x * blockDim.x + threadIdx.x) * 4;
    for (int i = base; i < n0; i += stride) cvt4(x0, h0, i);
    for (int i = base; i < n1; i += stride) cvt4(x1, h1, i);
}

// ---------------------------------------------------------------------------
// fp16 HMMA TN GEMM, cp.async 4-stage pipeline, 256 threads (8 warps),
// 2 CTAs/SM. CTA tile 128x128, BK=32, warp grid 4m x 2n, warp tile 32x64.
// C[m,n] = sum_k A[m,k]*B[n,k] + bias[n] (+ add[m,n]); out fp32 or fp16.
// Optional fused tail: fp32->fp16 convert of an unrelated array (W_dense),
// hidden under this kernel's DRAM headroom.
// ---------------------------------------------------------------------------
#define SSTRIDE 40
#define STAGES 4
#define BK 32
#define BUF_BYTES (128 * SSTRIDE * 2)        // 10240
#define STAGE_BYTES (2 * BUF_BYTES)          // 20480
#define GSM_TOTAL (STAGES * STAGE_BYTES)     // 81920

template <bool HALF_OUT>
__global__ __launch_bounds__(256, 2)
void gemm_hmma(const __half* __restrict__ Ag, const __half* __restrict__ Bg,
               const float* __restrict__ bias, const float* __restrict__ add,
               void* __restrict__ Cv, int M, int N, int K,
               const float* __restrict__ cvt_src, __half* __restrict__ cvt_dst, int cvt_n)
{
    extern __shared__ char smem[];
    const uint32_t sb = smem_u32(smem);

    const int tid  = threadIdx.x;
    const int wid  = tid >> 5;
    const int lane = tid & 31;
    const int bm = blockIdx.y * 128;
    const int bn = blockIdx.x * 128;

    const int warp_m = (wid & 3) * 32;     // 4 warps along M
    const int warp_n = (wid >> 2) * 64;    // 2 warps along N (tile 32x64)

    // loader mapping: thread -> row (0..127), 16-col half
    const int lrow = tid >> 1;
    const int lcol = (tid & 1) * 16;
    const __half* gA = Ag + (size_t)(bm + lrow) * K + lcol;
    const __half* gB = Bg + (size_t)(bn + lrow) * K + lcol;
    const uint32_t sdst = (uint32_t)(lrow * SSTRIDE + lcol) * 2;

    const int a_r = warp_m + (lane & 15);
    const int a_c = (lane >> 4) * 8;
    const int b_rr = (lane >> 4) * 8 + (lane & 7);
    const int b_c = ((lane >> 3) & 1) * 8;

    float acc[2][8][4];
#pragma unroll
    for (int i = 0; i < 2; i++)
#pragma unroll
        for (int j = 0; j < 8; j++)
#pragma unroll
            for (int e = 0; e < 4; e++) acc[i][j][e] = 0.0f;

    const int NCH = K >> 5;

    auto issue = [&](int ch) {
        const uint32_t base = sb + (uint32_t)(ch % STAGES) * STAGE_BYTES;
        const int ko = ch * BK;
        cp16(base + sdst,                  gA + ko);
        cp16(base + sdst + 16,             gA + ko + 8);
        cp16(base + BUF_BYTES + sdst,      gB + ko);
        cp16(base + BUF_BYTES + sdst + 16, gB + ko + 8);
        cp_commit();
    };

#pragma unroll
    for (int ch = 0; ch < STAGES - 1; ch++) issue(ch);

    for (int ch = 0; ch < NCH; ch++) {
        cp_wait<STAGES - 2>();
        __syncthreads();
        if (ch + STAGES - 1 < NCH) issue(ch + STAGES - 1);

        const uint32_t base = sb + (uint32_t)(ch % STAGES) * STAGE_BYTES;
        const uint32_t aA = base;
        const uint32_t aB = base + BUF_BYTES;

#pragma unroll
        for (int ks = 0; ks < 2; ks++) {
            const int kc = ks * 16;
            uint32_t ah[2][4], bh[8][2];
#pragma unroll
            for (int mt = 0; mt < 2; mt++) {
                const uint32_t off = (uint32_t)(((a_r + mt * 16) * SSTRIDE + kc + a_c) * 2);
                ldsm4(ah[mt], aA + off);
            }
#pragma unroll
            for (int ntp = 0; ntp < 4; ntp++) {
                const uint32_t off = (uint32_t)(((warp_n + ntp * 16 + b_rr) * SSTRIDE
                                                 + kc + b_c) * 2);
                uint32_t r[4];
                ldsm4(r, aB + off);
                bh[ntp * 2][0] = r[0]; bh[ntp * 2][1] = r[1];
                bh[ntp * 2 + 1][0] = r[2]; bh[ntp * 2 + 1][1] = r[3];
            }
#pragma unroll
            for (int mt = 0; mt < 2; mt++)
#pragma unroll
                for (int nt = 0; nt < 8; nt++)
                    mma16816(acc[mt][nt], ah[mt], bh[nt]);
        }
    }

    // epilogue
#pragma unroll
    for (int mt = 0; mt < 2; mt++) {
        const int r0 = bm + warp_m + mt * 16 + (lane >> 2);
#pragma unroll
        for (int nt = 0; nt < 8; nt++) {
            const int col = bn + warp_n + nt * 8 + (lane & 3) * 2;
            const float b0 = bias[col], b1 = bias[col + 1];
            const float* c = acc[mt][nt];
            const size_t o0 = (size_t)r0 * N + col;
            const size_t o1 = (size_t)(r0 + 8) * N + col;
            float2 v0 = make_float2(c[0] + b0, c[1] + b1);
            float2 v1 = make_float2(c[2] + b0, c[3] + b1);
            if (add != nullptr) {
                const float2 a0 = *(const float2*)&add[o0];
                const float2 a1 = *(const float2*)&add[o1];
                v0.x += a0.x; v0.y += a0.y;
                v1.x += a1.x; v1.y += a1.y;
            }
            if (HALF_OUT) {
                __half* C = (__half*)Cv;
                *(__half2*)&C[o0] = __floats2half2_rn(v0.x, v0.y);
                *(__half2*)&C[o1] = __floats2half2_rn(v1.x, v1.y);
            } else {
                float* C = (float*)Cv;
                *(float2*)&C[o0] = v0;
                *(float2*)&C[o1] = v1;
            }
        }
    }

    // fused tail convert (W_dense), hidden under this kernel's DRAM headroom.
    // No intra-grid ordering needed: the consumer is a later kernel launch.
    if (cvt_src != nullptr) {
        const int gtid = (blockIdx.y * gridDim.x + blockIdx.x) * blockDim.x + tid;
        const int gstride = gridDim.x * gridDim.y * blockDim.x;
        for (int i = gtid * 4; i < cvt_n; i += gstride * 4) cvt4(cvt_src, cvt_dst, i);
    }
}

// ---------------------------------------------------------------------------
// Tensor-core flash attention with ALiBi (fp16 inputs, fp32 softmax/accum).
// (unchanged from R11/R12 — passed at rel_err 4.1e-4)
// ---------------------------------------------------------------------------
#define VSTRIDE 136
#define KTILE_B (64 * VSTRIDE * 2)
#define STAGE_A (2 * KTILE_B + 256)
#define ATT_SMEM (2 * STAGE_A)

__global__ __launch_bounds__(128, 1)
void attn_hmma(const __half* __restrict__ qkv, const float* __restrict__ alibi,
               __half* __restrict__ ctx)
{
    extern __shared__ char smem[];
    const uint32_t sb = smem_u32(smem);
    const int h = blockIdx.y, qb = blockIdx.x;
    const int tid = threadIdx.x, wid = tid >> 5, lane = tid & 31;
    const int qw0 = qb * 64 + wid * 16;
    const int r0 = lane >> 2;
    const int c0 = (lane & 3) * 2;

    uint32_t qf[8][4];
    {
        const __half* qbase = qkv + (size_t)qw0 * QKV_N + h * 384;
#pragma unroll
        for (int ks = 0; ks < 8; ks++) {
            const int col = ks * 16 + c0;
            qf[ks][0] = *(const uint32_t*)(qbase + (size_t)r0 * QKV_N + col);
            qf[ks][1] = *(const uint32_t*)(qbase + (size_t)(r0 + 8) * QKV_N + col);
            qf[ks][2] = *(const uint32_t*)(qbase + (size_t)r0 * QKV_N + col + 8);
            qf[ks][3] = *(const uint32_t*)(qbase + (size_t)(r0 + 8) * QKV_N + col + 8);
        }
    }

    float oacc[16][4];
#pragma unroll
    for (int i = 0; i < 16; i++)
#pragma unroll
        for (int e = 0; e < 4; e++) oacc[i][e] = 0.0f;
    float mr0 = -INFINITY, mr1 = -INFINITY, ls0 = 0.0f, ls1 = 0.0f;

    const int nt = qb + 1;

    auto issue = [&](int t) {
        const uint32_t base = sb + (uint32_t)(t & 1) * STAGE_A;
        const int kv0 = t * 64;
        const int r = tid >> 1, chl = tid & 1;
        const __half* ksrc = qkv + (size_t)(kv0 + r) * QKV_N + h * 384 + 128 + chl * 64;
        const uint32_t kdst = base + (uint32_t)(r * VSTRIDE + chl * 64) * 2;
#pragma unroll
        for (int c = 0; c < 8; c++) {
            cp16(kdst + c * 16,           ksrc + c * 8);
            cp16(kdst + KTILE_B + c * 16, ksrc + 128 + c * 8);
        }
        if (tid < 16)
            cp16(base + 2 * KTILE_B + tid * 16,
                 alibi + (size_t)h * SEQ + kv0 + tid * 4);
        cp_commit();
    };

    issue(0);

    for (int t = 0; t < nt; t++) {
        cp_wait<0>();
        __syncthreads();
        if (t + 1 < nt) issue(t + 1);

        const uint32_t base = sb + (uint32_t)(t & 1) * STAGE_A;
        const uint32_t Ks = base, Vs = base + KTILE_B;
        const float* albuf = (const float*)(smem + (size_t)(t & 1) * STAGE_A + 2 * KTILE_B);

        float sacc[8][4];
#pragma unroll
        for (int i = 0; i < 8; i++)
#pragma unroll
            for (int e = 0; e < 4; e++) sacc[i][e] = 0.0f;

#pragma unroll
        for (int ks = 0; ks < 8; ks++) {
            const int kc = ks * 16;
#pragma unroll
            for (int ntp = 0; ntp < 4; ntp++) {
                uint32_t rr[4];
                const uint32_t addr = Ks +
                    (uint32_t)(((ntp * 16 + (lane >> 4) * 8 + (lane & 7)) * VSTRIDE
                                + kc + ((lane >> 3) & 1) * 8) * 2);
                ldsm4(rr, addr);
                uint32_t b0[2] = {rr[0], rr[1]}, b1[2] = {rr[2], rr[3]};
                mma16816(sacc[2 * ntp],     qf[ks], b0);
                mma16816(sacc[2 * ntp + 1], qf[ks], b1);
            }
        }

        const int kv0 = t * 64;
        const int qg0 = qw0 + r0, qg1 = qg0 + 8;
        float m0 = -INFINITY, m1 = -INFINITY;
#pragma unroll
        for (int n8 = 0; n8 < 8; n8++) {
            const int j0 = n8 * 8 + c0;
            const float a0 = albuf[j0], a1 = albuf[j0 + 1];
            const int jg0 = kv0 + j0;
            float v0 = sacc[n8][0] * INV_NORM + a0;
            float v1 = sacc[n8][1] * INV_NORM + a1;
            float v2 = sacc[n8][2] * INV_NORM + a0;
            float v3 = sacc[n8][3] * INV_NORM + a1;
            if (jg0     > qg0) v0 = -INFINITY;
            if (jg0 + 1 > qg0) v1 = -INFINITY;
            if (jg0     > qg1) v2 = -INFINITY;
            if (jg0 + 1 > qg1) v3 = -INFINITY;
            sacc[n8][0] = v0; sacc[n8][1] = v1; sacc[n8][2] = v2; sacc[n8][3] = v3;
            m0 = fmaxf(m0, fmaxf(v0, v1));
            m1 = fmaxf(m1, fmaxf(v2, v3));
        }
        m0 = fmaxf(m0, __shfl_xor_sync(0xffffffffu, m0, 1));
        m0 = fmaxf(m0, __shfl_xor_sync(0xffffffffu, m0, 2));
        m1 = fmaxf(m1, __shfl_xor_sync(0xffffffffu, m1, 1));
        m1 = fmaxf(m1, __shfl_xor_sync(0xffffffffu, m1, 2));
        const float nm0 = fmaxf(mr0, m0), nm1 = fmaxf(mr1, m1);
        const float f0 = __expf(mr0 - nm0), f1 = __expf(mr1 - nm1);
        mr0 = nm0; mr1 = nm1;
        ls0 *= f0; ls1 *= f1;
#pragma unroll
        for (int i = 0; i < 16; i++) {
            oacc[i][0] *= f0; oacc[i][1] *= f0;
            oacc[i][2] *= f1; oacc[i][3] *= f1;
        }

        uint32_t pf[4][4];
#pragma unroll
        for (int n8 = 0; n8 < 8; n8++) {
            const float p0 = __expf(sacc[n8][0] - nm0);
            const float p1 = __expf(sacc[n8][1] - nm0);
            const float p2 = __expf(sacc[n8][2] - nm1);
            const float p3 = __expf(sacc[n8][3] - nm1);
            ls0 += p0 + p1; ls1 += p2 + p3;
            __half2 h01 = __floats2half2_rn(p0, p1);
            __half2 h23 = __floats2half2_rn(p2, p3);
            const int ks = n8 >> 1, hi = n8 & 1;
            pf[ks][2 * hi]     = *(uint32_t*)&h01;
            pf[ks][2 * hi + 1] = *(uint32_t*)&h23;
        }

#pragma unroll
        for (int ks = 0; ks < 4; ks++) {
#pragma unroll
            for (int g = 0; g < 8; g++) {
                uint32_t rr[4];
                const uint32_t addr = Vs +
                    (uint32_t)(((ks * 16 + ((lane >> 3) & 1) * 8 + (lane & 7)) * VSTRIDE
                                + g * 16 + (lane >> 4) * 8) * 2);
                ldsm4t(rr, addr);
                uint32_t b0[2] = {rr[0], rr[1]}, b1[2] = {rr[2], rr[3]};
                mma16816(oacc[2 * g],     pf[ks], b0);
                mma16816(oacc[2 * g + 1], pf[ks], b1);
            }
        }
    }

    ls0 += __shfl_xor_sync(0xffffffffu, ls0, 1);
    ls0 += __shfl_xor_sync(0xffffffffu, ls0, 2);
    ls1 += __shfl_xor_sync(0xffffffffu, ls1, 1);
    ls1 += __shfl_xor_sync(0xffffffffu, ls1, 2);
    const float inv0 = 1.0f / ls0, inv1 = 1.0f / ls1;

    __half* out0 = ctx + (size_t)(qw0 + r0) * HID + h * HDIM;
    __half* out1 = out0 + (size_t)8 * HID;
#pragma unroll
    for (int nd = 0; nd < 16; nd++) {
        const int d = nd * 8 + c0;
        *(__half2*)(out0 + d) = __floats2half2_rn(oacc[nd][0] * inv0, oacc[nd][1] * inv0);
        *(__half2*)(out1 + d) = __floats2half2_rn(oacc[nd][2] * inv1, oacc[nd][3] * inv1);
    }
}

// ---------------------------------------------------------------------------
// Launch
// inputs: 0 hidden_states, 1 residual, 2 alibi, 3 attention_mask (unused),
//         4 W_qkv [12288,4096], 5 b_qkv, 6 W_dense [4096,4096], 7 b_dense
// ---------------------------------------------------------------------------
extern "C" void kernel_launch(void* const* d_in, const int* in_sizes, int n_in,
                              void* d_out, int out_size)
{
    const float* hs       = (const float*)d_in[0];
    const float* residual = (const float*)d_in[1];
    const float* alibi    = (const float*)d_in[2];
    const float* Wqkv     = (const float*)d_in[4];
    const float* bqkv     = (const float*)d_in[5];
    const float* Wd       = (const float*)d_in[6];
    const float* bd       = (const float*)d_in[7];
    float* out = (float*)d_out;

    __half *qkv_h, *wq_h, *wd_h, *a_h;
    cudaGetSymbolAddress((void**)&qkv_h, g_qkv_h);
    cudaGetSymbolAddress((void**)&wq_h, g_Wqkv_h);
    cudaGetSymbolAddress((void**)&wd_h, g_Wd_h);
    cudaGetSymbolAddress((void**)&a_h, g_A_h);

    cudaFuncSetAttribute(gemm_hmma<true>,  cudaFuncAttributeMaxDynamicSharedMemorySize, GSM_TOTAL);
    cudaFuncSetAttribute(gemm_hmma<false>, cudaFuncAttributeMaxDynamicSharedMemorySize, GSM_TOTAL);
    cudaFuncSetAttribute(attn_hmma, cudaFuncAttributeMaxDynamicSharedMemorySize, ATT_SMEM);

    // 0) convert W_qkv + hidden_states in one launch (W_dense fused into QKV GEMM tail)
    round16_dual_kernel<<<2048, 256>>>(Wqkv, wq_h, QKV_N * HID, hs, a_h, SEQ * HID);

    // 1) fused QKV projection -> fp16 qkv; tail-converts W_dense under DRAM headroom
    {
        dim3 grid(QKV_N / 128, SEQ / 128);
        gemm_hmma<true><<<grid, 256, GSM_TOTAL>>>(a_h, wq_h, bqkv, nullptr,
                                                  qkv_h, SEQ, QKV_N, HID,
                                                  Wd, wd_h, HID * HID);
    }
    // 2) tensor-core flash attention -> ctx fp16
    {
        dim3 grid(SEQ / 64, NHEAD);
        attn_hmma<<<grid, 128, ATT_SMEM>>>(qkv_h, alibi, a_h);
    }
    // 3) dense projection + bias + residual -> fp32 out
    {
        dim3 grid(HID / 128, SEQ / 128);
        gemm_hmma<false><<<grid, 256, GSM_TOTAL>>>(a_h, wd_h, bd, residual,
                                                   out, SEQ, HID, HID,
                                                   nullptr, nullptr, 0);
    }
}

// round 17
// speedup vs baseline: 1.3692x; 1.0434x over previous
#include <cuda_runtime.h>
#include <cuda_fp16.h>
#include <math.h>
#include <stdint.h>

// Problem constants (B=1)
#define SEQ   2048
#define HID   4096
#define NHEAD 32
#define HDIM  128
#define QKV_N 12288            // 3*HID
#define INV_NORM 0.08838834764831845f   // 1/sqrt(128)

// Scratch buffers (device globals; runtime alloc forbidden)
static __device__ __half g_qkv_h[(size_t)SEQ * QKV_N];
static __device__ __half g_Wqkv_h[(size_t)QKV_N * HID];
static __device__ __half g_Wd_h[(size_t)HID * HID];
static __device__ __half g_A_h[(size_t)SEQ * HID];   // hs fp16, later overwritten by ctx

// ---------------------------------------------------------------------------
// helpers
// ---------------------------------------------------------------------------
__device__ __forceinline__ uint32_t smem_u32(const void* p) {
    uint32_t a;
    asm("{ .reg .u64 t; cvta.to.shared.u64 t, %1; cvt.u32.u64 %0, t; }" : "=r"(a) : "l"(p));
    return a;
}
__device__ __forceinline__ void ldsm4(uint32_t* r, uint32_t addr) {
    asm volatile("ldmatrix.sync.aligned.m8n8.x4.shared.b16 {%0,%1,%2,%3}, [%4];"
                 : "=r"(r[0]), "=r"(r[1]), "=r"(r[2]), "=r"(r[3]) : "r"(addr));
}
__device__ __forceinline__ void ldsm4t(uint32_t* r, uint32_t addr) {
    asm volatile("ldmatrix.sync.aligned.m8n8.x4.trans.shared.b16 {%0,%1,%2,%3}, [%4];"
                 : "=r"(r[0]), "=r"(r[1]), "=r"(r[2]), "=r"(r[3]) : "r"(addr));
}
__device__ __forceinline__ void mma16816(float* c, const uint32_t* a, const uint32_t* b) {
    asm volatile(
        "mma.sync.aligned.m16n8k16.row.col.f32.f16.f16.f32 "
        "{%0,%1,%2,%3}, {%4,%5,%6,%7}, {%8,%9}, {%0,%1,%2,%3};"
        : "+f"(c[0]), "+f"(c[1]), "+f"(c[2]), "+f"(c[3])
        : "r"(a[0]), "r"(a[1]), "r"(a[2]), "r"(a[3]), "r"(b[0]), "r"(b[1]));
}
__device__ __forceinline__ void cp16(uint32_t dst, const void* src) {
    asm volatile("cp.async.cg.shared.global [%0], [%1], 16;" :: "r"(dst), "l"(src) : "memory");
}
__device__ __forceinline__ void cp_commit() {
    asm volatile("cp.async.commit_group;" ::: "memory");
}
template <int N>
__device__ __forceinline__ void cp_wait() {
    asm volatile("cp.async.wait_group %0;" :: "n"(N) : "memory");
}

__device__ __forceinline__ void cvt4(const float* __restrict__ x, __half* __restrict__ h, int i) {
    const float4 v = *(const float4*)(x + i);
    __half2 h0 = __floats2half2_rn(v.x, v.y);
    __half2 h1 = __floats2half2_rn(v.z, v.w);
    *(uint2*)(h + i) = make_uint2(*(uint32_t*)&h0, *(uint32_t*)&h1);
}

// ---------------------------------------------------------------------------
// fp32 -> fp16 round for TWO arrays in one launch (Wqkv + hs)
// ---------------------------------------------------------------------------
__global__ void round16_dual_kernel(const float* __restrict__ x0, __half* __restrict__ h0, int n0,
                                    const float* __restrict__ x1, __half* __restrict__ h1, int n1)
{
    const int stride = gridDim.x * blockDim.x * 4;
    const int base = (blockIdx.x * blockDim.x + threadIdx.x) * 4;
    for (int i = base; i < n0; i += stride) cvt4(x0, h0, i);
    for (int i = base; i < n1; i += stride) cvt4(x1, h1, i);
}

// ---------------------------------------------------------------------------
// fp16 HMMA TN GEMM, cp.async 4-stage pipeline, 256 threads (8 warps),
// 2 CTAs/SM. CTA tile 128x128, BK=32, warp grid 4m x 2n, warp tile 32x64.
// C[m,n] = sum_k A[m,k]*B[n,k] + bias[n] (+ add[m,n]); out fp32 or fp16.
// Optional fused tail: fp32->fp16 convert of W_dense under DRAM headroom.
// ---------------------------------------------------------------------------
#define SSTRIDE 40
#define STAGES 4
#define BK 32
#define BUF_BYTES (128 * SSTRIDE * 2)        // 10240
#define STAGE_BYTES (2 * BUF_BYTES)          // 20480
#define GSM_TOTAL (STAGES * STAGE_BYTES)     // 81920

template <bool HALF_OUT>
__global__ __launch_bounds__(256, 2)
void gemm_hmma(const __half* __restrict__ Ag, const __half* __restrict__ Bg,
               const float* __restrict__ bias, const float* __restrict__ add,
               void* __restrict__ Cv, int M, int N, int K,
               const float* __restrict__ cvt_src, __half* __restrict__ cvt_dst, int cvt_n)
{
    extern __shared__ char smem[];
    const uint32_t sb = smem_u32(smem);

    const int tid  = threadIdx.x;
    const int wid  = tid >> 5;
    const int lane = tid & 31;
    const int bm = blockIdx.y * 128;
    const int bn = blockIdx.x * 128;

    const int warp_m = (wid & 3) * 32;
    const int warp_n = (wid >> 2) * 64;

    const int lrow = tid >> 1;
    const int lcol = (tid & 1) * 16;
    const __half* gA = Ag + (size_t)(bm + lrow) * K + lcol;
    const __half* gB = Bg + (size_t)(bn + lrow) * K + lcol;
    const uint32_t sdst = (uint32_t)(lrow * SSTRIDE + lcol) * 2;

    const int a_r = warp_m + (lane & 15);
    const int a_c = (lane >> 4) * 8;
    const int b_rr = (lane >> 4) * 8 + (lane & 7);
    const int b_c = ((lane >> 3) & 1) * 8;

    float acc[2][8][4];
#pragma unroll
    for (int i = 0; i < 2; i++)
#pragma unroll
        for (int j = 0; j < 8; j++)
#pragma unroll
            for (int e = 0; e < 4; e++) acc[i][j][e] = 0.0f;

    const int NCH = K >> 5;

    auto issue = [&](int ch) {
        const uint32_t base = sb + (uint32_t)(ch % STAGES) * STAGE_BYTES;
        const int ko = ch * BK;
        cp16(base + sdst,                  gA + ko);
        cp16(base + sdst + 16,             gA + ko + 8);
        cp16(base + BUF_BYTES + sdst,      gB + ko);
        cp16(base + BUF_BYTES + sdst + 16, gB + ko + 8);
        cp_commit();
    };

#pragma unroll
    for (int ch = 0; ch < STAGES - 1; ch++) issue(ch);

    for (int ch = 0; ch < NCH; ch++) {
        cp_wait<STAGES - 2>();
        __syncthreads();
        if (ch + STAGES - 1 < NCH) issue(ch + STAGES - 1);

        const uint32_t base = sb + (uint32_t)(ch % STAGES) * STAGE_BYTES;
        const uint32_t aA = base;
        const uint32_t aB = base + BUF_BYTES;

#pragma unroll
        for (int ks = 0; ks < 2; ks++) {
            const int kc = ks * 16;
            uint32_t ah[2][4], bh[8][2];
#pragma unroll
            for (int mt = 0; mt < 2; mt++) {
                const uint32_t off = (uint32_t)(((a_r + mt * 16) * SSTRIDE + kc + a_c) * 2);
                ldsm4(ah[mt], aA + off);
            }
#pragma unroll
            for (int ntp = 0; ntp < 4; ntp++) {
                const uint32_t off = (uint32_t)(((warp_n + ntp * 16 + b_rr) * SSTRIDE
                                                 + kc + b_c) * 2);
                uint32_t r[4];
                ldsm4(r, aB + off);
                bh[ntp * 2][0] = r[0]; bh[ntp * 2][1] = r[1];
                bh[ntp * 2 + 1][0] = r[2]; bh[ntp * 2 + 1][1] = r[3];
            }
#pragma unroll
            for (int mt = 0; mt < 2; mt++)
#pragma unroll
                for (int nt = 0; nt < 8; nt++)
                    mma16816(acc[mt][nt], ah[mt], bh[nt]);
        }
    }

    // epilogue
#pragma unroll
    for (int mt = 0; mt < 2; mt++) {
        const int r0 = bm + warp_m + mt * 16 + (lane >> 2);
#pragma unroll
        for (int nt = 0; nt < 8; nt++) {
            const int col = bn + warp_n + nt * 8 + (lane & 3) * 2;
            const float b0 = bias[col], b1 = bias[col + 1];
            const float* c = acc[mt][nt];
            const size_t o0 = (size_t)r0 * N + col;
            const size_t o1 = (size_t)(r0 + 8) * N + col;
            float2 v0 = make_float2(c[0] + b0, c[1] + b1);
            float2 v1 = make_float2(c[2] + b0, c[3] + b1);
            if (add != nullptr) {
                const float2 a0 = *(const float2*)&add[o0];
                const float2 a1 = *(const float2*)&add[o1];
                v0.x += a0.x; v0.y += a0.y;
                v1.x += a1.x; v1.y += a1.y;
            }
            if (HALF_OUT) {
                __half* C = (__half*)Cv;
                *(__half2*)&C[o0] = __floats2half2_rn(v0.x, v0.y);
                *(__half2*)&C[o1] = __floats2half2_rn(v1.x, v1.y);
            } else {
                float* C = (float*)Cv;
                *(float2*)&C[o0] = v0;
                *(float2*)&C[o1] = v1;
            }
        }
    }

    // fused tail convert (W_dense) hidden under this kernel's DRAM headroom.
    if (cvt_src != nullptr) {
        const int gtid = (blockIdx.y * gridDim.x + blockIdx.x) * blockDim.x + tid;
        const int gstride = gridDim.x * gridDim.y * blockDim.x;
        for (int i = gtid * 4; i < cvt_n; i += gstride * 4) cvt4(cvt_src, cvt_dst, i);
    }
}

// ---------------------------------------------------------------------------
// Tensor-core flash attention with ALiBi (fp16 in, fp32 softmax/accum).
// grid = (SEQ/128, NHEAD), 256 threads (8 warps); warp owns 16 q rows.
// 8 warps share each 64-row K/V tile (2x warps, 1/2 gmem traffic vs R16).
// Lower-half warps skip fully-masked kv tiles.
// ---------------------------------------------------------------------------
#define VSTRIDE 136
#define KTILE_B (64 * VSTRIDE * 2)
#define STAGE_A (2 * KTILE_B + 256)
#define ATT_SMEM (2 * STAGE_A)

__global__ __launch_bounds__(256, 1)
void attn_hmma(const __half* __restrict__ qkv, const float* __restrict__ alibi,
               __half* __restrict__ ctx)
{
    extern __shared__ char smem[];
    const uint32_t sb = smem_u32(smem);
    const int h = blockIdx.y, qb = blockIdx.x;
    const int tid = threadIdx.x, wid = tid >> 5, lane = tid & 31;
    const int qw0 = qb * 128 + wid * 16;     // warp's first q row
    const int r0 = lane >> 2;
    const int c0 = (lane & 3) * 2;

    uint32_t qf[8][4];
    {
        const __half* qbase = qkv + (size_t)qw0 * QKV_N + h * 384;
#pragma unroll
        for (int ks = 0; ks < 8; ks++) {
            const int col = ks * 16 + c0;
            qf[ks][0] = *(const uint32_t*)(qbase + (size_t)r0 * QKV_N + col);
            qf[ks][1] = *(const uint32_t*)(qbase + (size_t)(r0 + 8) * QKV_N + col);
            qf[ks][2] = *(const uint32_t*)(qbase + (size_t)r0 * QKV_N + col + 8);
            qf[ks][3] = *(const uint32_t*)(qbase + (size_t)(r0 + 8) * QKV_N + col + 8);
        }
    }

    float oacc[16][4];
#pragma unroll
    for (int i = 0; i < 16; i++)
#pragma unroll
        for (int e = 0; e < 4; e++) oacc[i][e] = 0.0f;
    float mr0 = -INFINITY, mr1 = -INFINITY, ls0 = 0.0f, ls1 = 0.0f;

    const int nt = 2 * qb + 2;               // kv tiles covering [0, qb*128+128)

    // loader: 256 threads; row = tid>>2 (0..63), quarter = tid&3 (32 halves)
    auto issue = [&](int t) {
        const uint32_t base = sb + (uint32_t)(t & 1) * STAGE_A;
        const int kv0 = t * 64;
        const int r = tid >> 2, qd = tid & 3;
        const __half* ksrc = qkv + (size_t)(kv0 + r) * QKV_N + h * 384 + 128 + qd * 32;
        const uint32_t kdst = base + (uint32_t)(r * VSTRIDE + qd * 32) * 2;
#pragma unroll
        for (int c = 0; c < 4; c++) {
            cp16(kdst + c * 16,           ksrc + c * 8);
            cp16(kdst + KTILE_B + c * 16, ksrc + 128 + c * 8);   // V
        }
        if (tid < 16)
            cp16(base + 2 * KTILE_B + tid * 16,
                 alibi + (size_t)h * SEQ + kv0 + tid * 4);
        cp_commit();
    };

    issue(0);

    for (int t = 0; t < nt; t++) {
        cp_wait<0>();
        __syncthreads();
        if (t + 1 < nt) issue(t + 1);

        const int kv0 = t * 64;
        if (kv0 <= qw0 + 15) {               // skip fully-masked tiles (per-warp)
            const uint32_t base = sb + (uint32_t)(t & 1) * STAGE_A;
            const uint32_t Ks = base, Vs = base + KTILE_B;
            const float* albuf = (const float*)(smem + (size_t)(t & 1) * STAGE_A + 2 * KTILE_B);

            float sacc[8][4];
#pragma unroll
            for (int i = 0; i < 8; i++)
#pragma unroll
                for (int e = 0; e < 4; e++) sacc[i][e] = 0.0f;

#pragma unroll
            for (int ks = 0; ks < 8; ks++) {
                const int kc = ks * 16;
#pragma unroll
                for (int ntp = 0; ntp < 4; ntp++) {
                    uint32_t rr[4];
                    const uint32_t addr = Ks +
                        (uint32_t)(((ntp * 16 + (lane >> 4) * 8 + (lane & 7)) * VSTRIDE
                                    + kc + ((lane >> 3) & 1) * 8) * 2);
                    ldsm4(rr, addr);
                    uint32_t b0[2] = {rr[0], rr[1]}, b1[2] = {rr[2], rr[3]};
                    mma16816(sacc[2 * ntp],     qf[ks], b0);
                    mma16816(sacc[2 * ntp + 1], qf[ks], b1);
                }
            }

            const int qg0 = qw0 + r0, qg1 = qg0 + 8;
            float m0 = -INFINITY, m1 = -INFINITY;
#pragma unroll
            for (int n8 = 0; n8 < 8; n8++) {
                const int j0 = n8 * 8 + c0;
                const float a0 = albuf[j0], a1 = albuf[j0 + 1];
                const int jg0 = kv0 + j0;
                float v0 = sacc[n8][0] * INV_NORM + a0;
                float v1 = sacc[n8][1] * INV_NORM + a1;
                float v2 = sacc[n8][2] * INV_NORM + a0;
                float v3 = sacc[n8][3] * INV_NORM + a1;
                if (jg0     > qg0) v0 = -INFINITY;
                if (jg0 + 1 > qg0) v1 = -INFINITY;
                if (jg0     > qg1) v2 = -INFINITY;
                if (jg0 + 1 > qg1) v3 = -INFINITY;
                sacc[n8][0] = v0; sacc[n8][1] = v1; sacc[n8][2] = v2; sacc[n8][3] = v3;
                m0 = fmaxf(m0, fmaxf(v0, v1));
                m1 = fmaxf(m1, fmaxf(v2, v3));
            }
            m0 = fmaxf(m0, __shfl_xor_sync(0xffffffffu, m0, 1));
            m0 = fmaxf(m0, __shfl_xor_sync(0xffffffffu, m0, 2));
            m1 = fmaxf(m1, __shfl_xor_sync(0xffffffffu, m1, 1));
            m1 = fmaxf(m1, __shfl_xor_sync(0xffffffffu, m1, 2));
            const float nm0 = fmaxf(mr0, m0), nm1 = fmaxf(mr1, m1);
            const float f0 = __expf(mr0 - nm0), f1 = __expf(mr1 - nm1);
            mr0 = nm0; mr1 = nm1;
            ls0 *= f0; ls1 *= f1;
#pragma unroll
            for (int i = 0; i < 16; i++) {
                oacc[i][0] *= f0; oacc[i][1] *= f0;
                oacc[i][2] *= f1; oacc[i][3] *= f1;
            }

            uint32_t pf[4][4];
#pragma unroll
            for (int n8 = 0; n8 < 8; n8++) {
                const float p0 = __expf(sacc[n8][0] - nm0);
                const float p1 = __expf(sacc[n8][1] - nm0);
                const float p2 = __expf(sacc[n8][2] - nm1);
                const float p3 = __expf(sacc[n8][3] - nm1);
                ls0 += p0 + p1; ls1 += p2 + p3;
                __half2 h01 = __floats2half2_rn(p0, p1);
                __half2 h23 = __floats2half2_rn(p2, p3);
                const int ks = n8 >> 1, hi = n8 & 1;
                pf[ks][2 * hi]     = *(uint32_t*)&h01;
                pf[ks][2 * hi + 1] = *(uint32_t*)&h23;
            }

#pragma unroll
            for (int ks = 0; ks < 4; ks++) {
#pragma unroll
                for (int g = 0; g < 8; g++) {
                    uint32_t rr[4];
                    const uint32_t addr = Vs +
                        (uint32_t)(((ks * 16 + ((lane >> 3) & 1) * 8 + (lane & 7)) * VSTRIDE
                                    + g * 16 + (lane >> 4) * 8) * 2);
                    ldsm4t(rr, addr);
                    uint32_t b0[2] = {rr[0], rr[1]}, b1[2] = {rr[2], rr[3]};
                    mma16816(oacc[2 * g],     pf[ks], b0);
                    mma16816(oacc[2 * g + 1], pf[ks], b1);
                }
            }
        }
        __syncthreads();   // all warps done with buffer before next overwrite
    }

    ls0 += __shfl_xor_sync(0xffffffffu, ls0, 1);
    ls0 += __shfl_xor_sync(0xffffffffu, ls0, 2);
    ls1 += __shfl_xor_sync(0xffffffffu, ls1, 1);
    ls1 += __shfl_xor_sync(0xffffffffu, ls1, 2);
    const float inv0 = 1.0f / ls0, inv1 = 1.0f / ls1;

    __half* out0 = ctx + (size_t)(qw0 + r0) * HID + h * HDIM;
    __half* out1 = out0 + (size_t)8 * HID;
#pragma unroll
    for (int nd = 0; nd < 16; nd++) {
        const int d = nd * 8 + c0;
        *(__half2*)(out0 + d) = __floats2half2_rn(oacc[nd][0] * inv0, oacc[nd][1] * inv0);
        *(__half2*)(out1 + d) = __floats2half2_rn(oacc[nd][2] * inv1, oacc[nd][3] * inv1);
    }
}

// ---------------------------------------------------------------------------
// Launch
// inputs: 0 hidden_states, 1 residual, 2 alibi, 3 attention_mask (unused),
//         4 W_qkv [12288,4096], 5 b_qkv, 6 W_dense [4096,4096], 7 b_dense
// ---------------------------------------------------------------------------
extern "C" void kernel_launch(void* const* d_in, const int* in_sizes, int n_in,
                              void* d_out, int out_size)
{
    const float* hs       = (const float*)d_in[0];
    const float* residual = (const float*)d_in[1];
    const float* alibi    = (const float*)d_in[2];
    const float* Wqkv     = (const float*)d_in[4];
    const float* bqkv     = (const float*)d_in[5];
    const float* Wd       = (const float*)d_in[6];
    const float* bd       = (const float*)d_in[7];
    float* out = (float*)d_out;

    __half *qkv_h, *wq_h, *wd_h, *a_h;
    cudaGetSymbolAddress((void**)&qkv_h, g_qkv_h);
    cudaGetSymbolAddress((void**)&wq_h, g_Wqkv_h);
    cudaGetSymbolAddress((void**)&wd_h, g_Wd_h);
    cudaGetSymbolAddress((void**)&a_h, g_A_h);

    cudaFuncSetAttribute(gemm_hmma<true>,  cudaFuncAttributeMaxDynamicSharedMemorySize, GSM_TOTAL);
    cudaFuncSetAttribute(gemm_hmma<false>, cudaFuncAttributeMaxDynamicSharedMemorySize, GSM_TOTAL);
    cudaFuncSetAttribute(attn_hmma, cudaFuncAttributeMaxDynamicSharedMemorySize, ATT_SMEM);

    // 0) convert W_qkv + hidden_states in one launch
    round16_dual_kernel<<<2048, 256>>>(Wqkv, wq_h, QKV_N * HID, hs, a_h, SEQ * HID);

    // 1) fused QKV projection -> fp16 qkv; tail-converts W_dense
    {
        dim3 grid(QKV_N / 128, SEQ / 128);
        gemm_hmma<true><<<grid, 256, GSM_TOTAL>>>(a_h, wq_h, bqkv, nullptr,
                                                  qkv_h, SEQ, QKV_N, HID,
                                                  Wd, wd_h, HID * HID);
    }
    // 2) tensor-core flash attention -> ctx fp16 (128-query CTAs, 8 warps)
    {
        dim3 grid(SEQ / 128, NHEAD);
        attn_hmma<<<grid, 256, ATT_SMEM>>>(qkv_h, alibi, a_h);
    }
    // 3) dense projection + bias + residual -> fp32 out
    {
        dim3 grid(HID / 128, SEQ / 128);
        gemm_hmma<false><<<grid, 256, GSM_TOTAL>>>(a_h, wd_h, bd, residual,
                                                   out, SEQ, HID, HID,
                                                   nullptr, nullptr, 0);
    }
}